// round 7
// baseline (speedup 1.0000x reference)
#include <cuda_runtime.h>
#include <cstdint>
#include <math.h>

// ---------------------------------------------------------------------------
// B=32, P=1024, HID=512, H=8, D=64, MEM=64, RANK=64
// coeffs[b,p,q] = sum_{i<16} F[b,p,i]*Hh[b,q,i] + Hh[b,q,16]
//
// Softmax stats via 24-node Chebyshev interpolation of f(a)=Σe^{ax}, g=f'
// (786K exps instead of 16.7M). Features a1(x),a2(x) via 4096-pt lookup table.
// ---------------------------------------------------------------------------

#define Bx 32
#define Pn 1024
#define Hn 8
#define NCH 24
#define NG 4096

__device__ float g_G[17 * 17];
__device__ float g_a[Hn * 64];          // a[h][m]
__device__ float g_amax;
__device__ float g_nodes[NCH];          // Chebyshev nodes (in a units)
__device__ float g_C[NCH * NCH];        // coeff transform (2/N)cos(k theta_j)
__device__ float g_xr[2];               // x range lo, hi
__device__ float g_Fn[Bx * NCH];        // f at nodes
__device__ float g_Gn[Bx * NCH];        // g at nodes
__device__ float g_S1[Bx * Hn];
__device__ float g_S2[Bx * Hn];
__device__ float g_tab[(NG + 1) * 16];  // a1(x) [h<8], a2(x) [h>=8]
__device__ float g_F[(size_t)Bx * 16 * Pn];   // [b][i][p]
__device__ float g_Hh[(size_t)Bx * 17 * Pn];  // [b][i][p]

// ---------------------------------------------------------------------------
// Kernel 1: prep. block0 = G matrix; block1 = a[h,m], amax, nodes, C;
// block2 = global x range.
// ---------------------------------------------------------------------------
__global__ void __launch_bounds__(512) kPrep(
    const float* __restrict__ x,
    const float* __restrict__ w_k, const float* __restrict__ w_mem,
    const float* __restrict__ w_u, const float* __restrict__ b_u,
    const float* __restrict__ w_v2, const float* __restrict__ b_v2,
    const float* __restrict__ w_v, const float* __restrict__ b_v)
{
    const int tid = threadIdx.x;

    if (blockIdx.x == 0) {
        __shared__ float sWU[64][17];
        __shared__ float sWV[64][17];
        for (int idx = tid; idx < 64 * 16; idx += 512) {
            int r = idx >> 4, i = idx & 15, hh = i & 7;
            const float* col = (i < 8) ? w_v : b_v;
            float su = 0.f, sv = 0.f;
            #pragma unroll 8
            for (int d = 0; d < 64; d++) {
                float c = col[hh * 64 + d];
                su = fmaf(w_u[r * 512 + hh * 64 + d], c, su);
                sv = fmaf(w_v2[r * 512 + hh * 64 + d], c, sv);
            }
            sWU[r][i] = su;
            sWV[r][i] = sv;
        }
        if (tid < 64) { sWU[tid][16] = b_u[tid]; sWV[tid][16] = b_v2[tid]; }
        __syncthreads();
        for (int idx = tid; idx < 289; idx += 512) {
            int i = idx / 17, j = idx % 17;
            float s = 0.f;
            #pragma unroll 8
            for (int r = 0; r < 64; r++)
                s = fmaf(sWU[r][i], sWV[r][j], s);
            g_G[idx] = s;
        }
    } else if (blockIdx.x == 1) {
        __shared__ float sred[16];
        __shared__ float sAmax;
        // a[h][m], one thread per (h,m)
        int h = tid >> 6, m = tid & 63;
        float s = 0.f;
        #pragma unroll 8
        for (int d = 0; d < 64; d++)
            s = fmaf(w_k[h * 64 + d], w_mem[m * 64 + d], s);
        g_a[tid] = s;
        // amax = max |a|
        float am = fabsf(s);
        #pragma unroll
        for (int off = 16; off; off >>= 1)
            am = fmaxf(am, __shfl_down_sync(0xffffffffu, am, off));
        if ((tid & 31) == 0) sred[tid >> 5] = am;
        __syncthreads();
        if (tid == 0) {
            float M = sred[0];
            #pragma unroll
            for (int i = 1; i < 16; i++) M = fmaxf(M, sred[i]);
            g_amax = M;
            sAmax = M;
        }
        __syncthreads();
        const float PI = 3.14159265358979323846f;
        if (tid < NCH)
            g_nodes[tid] = sAmax * cosf((2 * tid + 1) * (PI / (2 * NCH)));
        // FIX: 576 entries > 512 threads -> strided loop
        for (int idx = tid; idx < NCH * NCH; idx += 512) {
            int k = idx / NCH, j = idx % NCH;
            g_C[idx] = (2.0f / NCH) * cosf(k * (2 * j + 1) * (PI / (2 * NCH)));
        }
    } else {
        __shared__ float sred2[32];
        float mx = -INFINITY, mn = INFINITY;
        for (int i = tid; i < Bx * Pn; i += 512) {
            float v = x[i];
            mx = fmaxf(mx, v); mn = fminf(mn, v);
        }
        #pragma unroll
        for (int off = 16; off; off >>= 1) {
            mx = fmaxf(mx, __shfl_down_sync(0xffffffffu, mx, off));
            mn = fminf(mn, __shfl_down_sync(0xffffffffu, mn, off));
        }
        if ((tid & 31) == 0) { sred2[tid >> 5] = mx; sred2[16 + (tid >> 5)] = mn; }
        __syncthreads();
        if (tid == 0) {
            float M = sred2[0], m2 = sred2[16];
            #pragma unroll
            for (int i = 1; i < 16; i++) {
                M = fmaxf(M, sred2[i]); m2 = fminf(m2, sred2[16 + i]);
            }
            g_xr[0] = m2 - 1e-3f;
            g_xr[1] = M + 1e-3f;
        }
    }
}

// ---------------------------------------------------------------------------
// Kernel 2: node evaluation. grid (NCH, Bx), 256 thr.
// F_j = sum_p e^{a_j x_p},  G_j = sum_p x_p e^{a_j x_p}
// ---------------------------------------------------------------------------
__global__ void __launch_bounds__(256) kNodes(const float* __restrict__ x)
{
    const int j = blockIdx.x, b = blockIdx.y;
    const int tid = threadIdx.x;
    __shared__ float sred[16];

    const float a2 = g_nodes[j] * 1.44269504088896f;  // log2(e)
    float num = 0.f, den = 0.f;
    #pragma unroll
    for (int r = 0; r < 4; r++) {
        float xv = x[b * Pn + tid + r * 256];
        float e = exp2f(a2 * xv);
        den += e;
        num = fmaf(xv, e, num);
    }
    #pragma unroll
    for (int off = 16; off; off >>= 1) {
        num += __shfl_down_sync(0xffffffffu, num, off);
        den += __shfl_down_sync(0xffffffffu, den, off);
    }
    if ((tid & 31) == 0) { sred[tid >> 5] = den; sred[8 + (tid >> 5)] = num; }
    __syncthreads();
    if (tid == 0) {
        float F = 0.f, G = 0.f;
        #pragma unroll
        for (int i = 0; i < 8; i++) { F += sred[i]; G += sred[8 + i]; }
        g_Fn[b * NCH + j] = F;
        g_Gn[b * NCH + j] = G;
    }
}

// ---------------------------------------------------------------------------
// Kernel 3: build a1/a2 lookup table over x. grid (17, 8) x 256 thr.
// ---------------------------------------------------------------------------
__global__ void __launch_bounds__(256) kTab(
    const float* __restrict__ w_q, const float* __restrict__ b_q,
    const float* __restrict__ w_v, const float* __restrict__ b_v)
{
    __shared__ float swq[64], sbq[64], swv[64], sbv[64];
    const int h = blockIdx.y;
    const int tid = threadIdx.x;
    if (tid < 64) {
        swq[tid] = w_q[h * 64 + tid];
        sbq[tid] = b_q[h * 64 + tid];
        swv[tid] = w_v[h * 64 + tid];
        sbv[tid] = b_v[h * 64 + tid];
    }
    __syncthreads();

    const int i = blockIdx.x * 256 + tid;
    if (i > NG) return;
    const float xlo = g_xr[0], xhi = g_xr[1];
    const float xv = xlo + (xhi - xlo) * ((float)i / NG);

    float a1 = 0.f, a2 = 0.f;
    #pragma unroll 8
    for (int d = 0; d < 64; d++) {
        float v = fmaf(xv, swq[d], sbq[d]);
        float qf = (v > 0.f) ? (v + 1.f) : __expf(v);
        a1 = fmaf(qf, swv[d], a1);
        a2 = fmaf(qf, sbv[d], a2);
    }
    g_tab[i * 16 + h] = a1;
    g_tab[i * 16 + 8 + h] = a2;
}

// ---------------------------------------------------------------------------
// Kernel 4: Clenshaw eval of T[m]=g/f at a[h,m]; S1,S2 per (b,h).
// grid (Bx), 512 thr, thread=(h,m).
// ---------------------------------------------------------------------------
__global__ void __launch_bounds__(512) kT()
{
    __shared__ float sC[NCH * NCH];
    __shared__ float sFn[NCH], sGn[NCH];
    __shared__ float cf[NCH], cg[NCH];
    __shared__ float sTm[512], sT2[512];

    const int b = blockIdx.x, tid = threadIdx.x;
    // FIX: 576 entries > 512 threads -> strided loop
    for (int idx = tid; idx < NCH * NCH; idx += 512) sC[idx] = g_C[idx];
    if (tid < NCH) { sFn[tid] = g_Fn[b * NCH + tid]; sGn[tid] = g_Gn[b * NCH + tid]; }
    __syncthreads();
    if (tid < 2 * NCH) {
        int k = tid % NCH;
        const float* src = (tid < NCH) ? sFn : sGn;
        float s = 0.f;
        #pragma unroll
        for (int j = 0; j < NCH; j++)
            s = fmaf(sC[k * NCH + j], src[j], s);
        if (tid < NCH) cf[k] = s; else cg[k] = s;
    }
    __syncthreads();

    const float t = g_a[tid] / g_amax;
    const float t2 = 2.f * t;
    float b1 = 0.f, b2 = 0.f, d1 = 0.f, d2 = 0.f;
    #pragma unroll
    for (int k = NCH - 1; k >= 1; k--) {
        float nb = fmaf(t2, b1, -b2) + cf[k];
        b2 = b1; b1 = nb;
        float nd = fmaf(t2, d1, -d2) + cg[k];
        d2 = d1; d1 = nd;
    }
    const float f = fmaf(t, b1, -b2) + 0.5f * cf[0];
    const float g = fmaf(t, d1, -d2) + 0.5f * cg[0];
    const float T = g / f;
    sTm[tid] = T;
    sT2[tid] = T * T;
    __syncthreads();

    const int w = tid >> 5, lane = tid & 31;
    if (w < 8) {
        float s1 = sTm[w * 64 + lane] + sTm[w * 64 + 32 + lane];
        float s2 = sT2[w * 64 + lane] + sT2[w * 64 + 32 + lane];
        #pragma unroll
        for (int off = 16; off; off >>= 1) {
            s1 += __shfl_down_sync(0xffffffffu, s1, off);
            s2 += __shfl_down_sync(0xffffffffu, s2, off);
        }
        if (lane == 0) { g_S1[b * Hn + w] = s1; g_S2[b * Hn + w] = s2; }
    }
}

// ---------------------------------------------------------------------------
// Kernel 5: features via table lookup. grid (Pn/64, Bx), 512 thr.
// ---------------------------------------------------------------------------
__global__ void __launch_bounds__(512) kFeat(const float* __restrict__ x)
{
    __shared__ float sG[289];
    __shared__ float sS1[8], sS2[8];
    __shared__ float sF[17][64];
    __shared__ float sxv[64];

    const int b = blockIdx.y, tid = threadIdx.x;
    const int p0 = blockIdx.x * 64;

    if (tid < 289) sG[tid] = g_G[tid];
    if (tid < 8) { sS1[tid] = g_S1[b * Hn + tid]; sS2[tid] = g_S2[b * Hn + tid]; }
    if (tid < 64) sxv[tid] = x[b * Pn + p0 + tid];
    __syncthreads();

    const int h = tid >> 6, pl = tid & 63;
    const float xlo = g_xr[0], xhi = g_xr[1];
    const float invh = (float)NG / (xhi - xlo);
    float u = (sxv[pl] - xlo) * invh;
    u = fminf(fmaxf(u, 0.f), (float)NG - 0.001f);
    const int i0 = (int)u;
    const float fr = u - (float)i0;
    const float* t0 = &g_tab[i0 * 16 + h];
    const float* t1 = &g_tab[(i0 + 1) * 16 + h];
    const float a1 = fmaf(fr, t1[0] - t0[0], t0[0]);
    const float a2 = fmaf(fr, t1[8] - t0[8], t0[8]);

    const float s1 = sS1[h], s2 = sS2[h];
    sF[h][pl]     = fmaf(a1, s2, a2 * s1);   // alpha
    sF[8 + h][pl] = fmaf(a1, s1, 64.f * a2); // beta
    if (h == 0) sF[16][pl] = 1.f;
    __syncthreads();

    {
        size_t baseF = ((size_t)b * 16) * Pn + p0;
        int i = tid >> 6, pl2 = tid & 63;
        g_F[baseF + (size_t)i * Pn + pl2] = sF[i][pl2];
        g_F[baseF + (size_t)(i + 8) * Pn + pl2] = sF[i + 8][pl2];
    }
    {
        size_t baseH = ((size_t)b * 17) * Pn + p0;
        for (int o = tid; o < 17 * 64; o += 512) {
            int i = o >> 6, pl2 = o & 63;
            float s = 0.f;
            #pragma unroll
            for (int j = 0; j < 17; j++)
                s = fmaf(sG[i * 17 + j], sF[j][pl2], s);
            g_Hh[baseH + (size_t)i * Pn + pl2] = s;
        }
    }
}

// ---------------------------------------------------------------------------
// Kernel 6: bilinear GEMM (round-5 version, known good).
// ---------------------------------------------------------------------------
#define FMA2(acc64, a64, b64) \
    asm("fma.rn.f32x2 %0, %1, %2, %0;" : "+l"(acc64) : "l"(a64), "l"(b64))
#define UNPACK2(lo, hi, in64) do { \
    unsigned _u0, _u1; \
    asm("mov.b64 {%0, %1}, %2;" : "=r"(_u0), "=r"(_u1) : "l"(in64)); \
    lo = __uint_as_float(_u0); hi = __uint_as_float(_u1); } while (0)

__global__ void __launch_bounds__(256) kGemm(float* __restrict__ out)
{
    const int b = blockIdx.z;
    const int tq0 = blockIdx.x * 64;
    const int tp0 = blockIdx.y * 128;

    __shared__ __align__(16) float sFd[16][256];
    __shared__ __align__(16) float sHh[17][64];

    const int tid = threadIdx.x;
    const int lane = tid & 31, w = tid >> 5;
    const float* Fb = g_F + ((size_t)b * 16) * Pn;
    const float* Hb = g_Hh + ((size_t)b * 17) * Pn;

    #pragma unroll
    for (int rep = 0; rep < 2; rep++) {
        int idx = tid + rep * 256;
        int row = idx >> 5, c4 = (idx & 31) << 2;
        float4 v = *(const float4*)&Fb[(size_t)row * Pn + tp0 + c4];
        *(float4*)&sFd[row][c4 * 2]     = make_float4(v.x, v.x, v.y, v.y);
        *(float4*)&sFd[row][c4 * 2 + 4] = make_float4(v.z, v.z, v.w, v.w);
    }
    {
        int row = tid >> 4, c4 = (tid & 15) << 2;
        *(float4*)&sHh[row][c4] = *(const float4*)&Hb[(size_t)row * Pn + tq0 + c4];
        if (tid < 16) {
            int idx2 = tid + 256;
            int row2 = idx2 >> 4, c42 = (idx2 & 15) << 2;
            *(float4*)&sHh[row2][c42] = *(const float4*)&Hb[(size_t)row2 * Pn + tq0 + c42];
        }
    }
    __syncthreads();

    unsigned long long bq[16];
    #pragma unroll
    for (int k = 0; k < 16; k++)
        bq[k] = *(const unsigned long long*)&sHh[k][2 * lane];
    const unsigned long long hbias = *(const unsigned long long*)&sHh[16][2 * lane];

    unsigned long long acc[16];
    #pragma unroll
    for (int r = 0; r < 16; r++) acc[r] = hbias;

    const int rowbase = w * 16;
    #pragma unroll
    for (int k = 0; k < 16; k++) {
        const float* fr = &sFd[k][rowbase * 2];
        #pragma unroll
        for (int rp = 0; rp < 8; rp++) {
            ulonglong2 ad = *(const ulonglong2*)&fr[rp * 4];
            FMA2(acc[2 * rp],     ad.x, bq[k]);
            FMA2(acc[2 * rp + 1], ad.y, bq[k]);
        }
    }

    float* outb = out + (size_t)b * Pn * Pn + (size_t)(tp0 + rowbase) * Pn + tq0 + 2 * lane;
    #pragma unroll
    for (int r = 0; r < 16; r++) {
        float2 v;
        UNPACK2(v.x, v.y, acc[r]);
        *(float2*)&outb[(size_t)r * Pn] = v;
    }
}

// ---------------------------------------------------------------------------
// inputs: 0 x, 1 w_q, 2 b_q, 3 w_k, 4 b_k(unused), 5 w_v, 6 b_v, 7 w_mem,
//         8 w_u, 9 b_u, 10 w_v2, 11 b_v2
// ---------------------------------------------------------------------------
extern "C" void kernel_launch(void* const* d_in, const int* in_sizes, int n_in,
                              void* d_out, int out_size)
{
    const float* x    = (const float*)d_in[0];
    const float* w_q  = (const float*)d_in[1];
    const float* b_q  = (const float*)d_in[2];
    const float* w_k  = (const float*)d_in[3];
    const float* w_v  = (const float*)d_in[5];
    const float* b_v  = (const float*)d_in[6];
    const float* w_mem = (const float*)d_in[7];
    const float* w_u  = (const float*)d_in[8];
    const float* b_u  = (const float*)d_in[9];
    const float* w_v2 = (const float*)d_in[10];
    const float* b_v2 = (const float*)d_in[11];
    float* out = (float*)d_out;

    kPrep<<<3, 512>>>(x, w_k, w_mem, w_u, b_u, w_v2, b_v2, w_v, b_v);
    kNodes<<<dim3(NCH, Bx), 256>>>(x);
    kTab<<<dim3(17, Hn), 256>>>(w_q, b_q, w_v, b_v);
    kT<<<Bx, 512>>>();
    kFeat<<<dim3(Pn / 64, Bx), 512>>>(x);
    kGemm<<<dim3(Pn / 64, Pn / 128, Bx), 256>>>(out);
}

// round 8
// speedup vs baseline: 1.6780x; 1.6780x over previous
#include <cuda_runtime.h>
#include <cstdint>
#include <math.h>

// ---------------------------------------------------------------------------
// B=32, P=1024, HID=512, H=8, D=64, MEM=64, RANK=64
// coeffs[b,p,q] = sum_{i<16} F[b,p,i]*Hh[b,q,i] + Hh[b,q,16]
// Softmax stats via 24-node Chebyshev interpolation of f(a)=Σe^{ax}, g=f',
// fully fused into ONE prelude kernel (3 launches total).
// ---------------------------------------------------------------------------

#define Bx 32
#define Pn 1024
#define Hn 8
#define NCH 24

__device__ float g_G[17 * 17];
__device__ float g_S1[Bx * Hn];
__device__ float g_S2[Bx * Hn];
__device__ float g_F[(size_t)Bx * 16 * Pn];   // [b][i][p]
__device__ float g_Hh[(size_t)Bx * 17 * Pn];  // [b][i][p]

// ---------------------------------------------------------------------------
// Kernel 1: fused prelude.
// blocks 0..31: per-batch Chebyshev stats -> S1[b,h], S2[b,h]
// block 32:     17x17 bilinear form G
// ---------------------------------------------------------------------------
__global__ void __launch_bounds__(512) kPre(
    const float* __restrict__ x,
    const float* __restrict__ w_k, const float* __restrict__ w_mem,
    const float* __restrict__ w_u, const float* __restrict__ b_u,
    const float* __restrict__ w_v2, const float* __restrict__ b_v2,
    const float* __restrict__ w_v, const float* __restrict__ b_v)
{
    const int tid = threadIdx.x;
    const int lane = tid & 31, wid = tid >> 5;
    const float PI = 3.14159265358979323846f;

    if (blockIdx.x == 32) {
        // ---- G matrix ----
        __shared__ float sWU[64][17];
        __shared__ float sWV[64][17];
        for (int idx = tid; idx < 64 * 16; idx += 512) {
            int r = idx >> 4, i = idx & 15, hh = i & 7;
            const float* col = (i < 8) ? w_v : b_v;
            float su = 0.f, sv = 0.f;
            #pragma unroll 8
            for (int d = 0; d < 64; d++) {
                float c = col[hh * 64 + d];
                su = fmaf(w_u[r * 512 + hh * 64 + d], c, su);
                sv = fmaf(w_v2[r * 512 + hh * 64 + d], c, sv);
            }
            sWU[r][i] = su;
            sWV[r][i] = sv;
        }
        if (tid < 64) { sWU[tid][16] = b_u[tid]; sWV[tid][16] = b_v2[tid]; }
        __syncthreads();
        for (int idx = tid; idx < 289; idx += 512) {
            int i = idx / 17, j = idx % 17;
            float s = 0.f;
            #pragma unroll 8
            for (int r = 0; r < 64; r++)
                s = fmaf(sWU[r][i], sWV[r][j], s);
            g_G[idx] = s;
        }
        return;
    }

    // ---- per-batch Chebyshev stats ----
    const int b = blockIdx.x;
    __shared__ float sx[Pn];
    __shared__ float sFn[NCH], sGn[NCH];
    __shared__ float scf[NCH], scg[NCH];
    __shared__ float sNodes[NCH];
    __shared__ float sred[16];
    __shared__ float sAmax;
    __shared__ float sTm[512], sT2[512];

    sx[tid] = x[b * Pn + tid];
    sx[tid + 512] = x[b * Pn + tid + 512];

    // a[h,m], thread = (h,m)
    const int h = tid >> 6, m = tid & 63;
    float a = 0.f;
    #pragma unroll 8
    for (int d = 0; d < 64; d++)
        a = fmaf(w_k[h * 64 + d], w_mem[m * 64 + d], a);

    // amax = max |a| over block
    float am = fabsf(a);
    #pragma unroll
    for (int off = 16; off; off >>= 1)
        am = fmaxf(am, __shfl_down_sync(0xffffffffu, am, off));
    if (lane == 0) sred[wid] = am;
    __syncthreads();
    if (tid == 0) {
        float M = sred[0];
        #pragma unroll
        for (int i = 1; i < 16; i++) M = fmaxf(M, sred[i]);
        sAmax = M;
    }
    __syncthreads();
    const float amax = sAmax;
    if (tid < NCH)
        sNodes[tid] = amax * cosf((2 * tid + 1) * (PI / (2 * NCH)));
    __syncthreads();

    // node sums: warp wid handles nodes j = wid, wid+16
    for (int j = wid; j < NCH; j += 16) {
        const float aj = sNodes[j] * 1.44269504088896f;  // log2(e)
        float num = 0.f, den = 0.f;
        #pragma unroll 8
        for (int p = lane; p < Pn; p += 32) {
            float xv = sx[p];
            float e = exp2f(aj * xv);
            den += e;
            num = fmaf(xv, e, num);
        }
        #pragma unroll
        for (int off = 16; off; off >>= 1) {
            num += __shfl_down_sync(0xffffffffu, num, off);
            den += __shfl_down_sync(0xffffffffu, den, off);
        }
        if (lane == 0) { sFn[j] = den; sGn[j] = num; }
    }
    __syncthreads();

    // Chebyshev coefficient transform (threads 0..47)
    if (tid < 2 * NCH) {
        const int k = (tid < NCH) ? tid : (tid - NCH);
        const float* src = (tid < NCH) ? sFn : sGn;
        float s = 0.f;
        #pragma unroll
        for (int j = 0; j < NCH; j++)
            s = fmaf((2.0f / NCH) * cosf(k * (2 * j + 1) * (PI / (2 * NCH))), src[j], s);
        if (tid < NCH) scf[k] = s; else scg[k] = s;
    }
    __syncthreads();

    // Clenshaw at t = a/amax -> T[h,m]
    const float t = a / amax;
    const float t2 = 2.f * t;
    float b1 = 0.f, b2 = 0.f, d1 = 0.f, d2 = 0.f;
    #pragma unroll
    for (int k = NCH - 1; k >= 1; k--) {
        float nb = fmaf(t2, b1, -b2) + scf[k];
        b2 = b1; b1 = nb;
        float nd = fmaf(t2, d1, -d2) + scg[k];
        d2 = d1; d1 = nd;
    }
    const float f = fmaf(t, b1, -b2) + 0.5f * scf[0];
    const float g = fmaf(t, d1, -d2) + 0.5f * scg[0];
    const float T = g / f;
    sTm[tid] = T;
    sT2[tid] = T * T;
    __syncthreads();

    if (wid < 8) {
        float s1 = sTm[wid * 64 + lane] + sTm[wid * 64 + 32 + lane];
        float s2 = sT2[wid * 64 + lane] + sT2[wid * 64 + 32 + lane];
        #pragma unroll
        for (int off = 16; off; off >>= 1) {
            s1 += __shfl_down_sync(0xffffffffu, s1, off);
            s2 += __shfl_down_sync(0xffffffffu, s2, off);
        }
        if (lane == 0) { g_S1[b * Hn + wid] = s1; g_S2[b * Hn + wid] = s2; }
    }
}

// ---------------------------------------------------------------------------
// Kernel 2: features (direct elu, R5 version). grid (Pn/64, Bx), 512 thr.
// ---------------------------------------------------------------------------
__global__ void __launch_bounds__(512) kFeat(
    const float* __restrict__ x,
    const float* __restrict__ w_q, const float* __restrict__ b_q,
    const float* __restrict__ w_v, const float* __restrict__ b_v)
{
    __shared__ float swq[512], sbq[512], swv[512], sbv[512];
    __shared__ float sG[289];
    __shared__ float sS1[8], sS2[8];
    __shared__ float sF[17][64];
    __shared__ float sxv[64];

    const int b = blockIdx.y, tid = threadIdx.x;
    const int p0 = blockIdx.x * 64;

    swq[tid] = w_q[tid]; sbq[tid] = b_q[tid];
    swv[tid] = w_v[tid]; sbv[tid] = b_v[tid];
    if (tid < 289) sG[tid] = g_G[tid];
    if (tid < 8) { sS1[tid] = g_S1[b * Hn + tid]; sS2[tid] = g_S2[b * Hn + tid]; }
    if (tid < 64) sxv[tid] = x[b * Pn + p0 + tid];
    __syncthreads();

    const int h = tid >> 6, pl = tid & 63;
    const float xv = sxv[pl];
    const float4* wq4 = (const float4*)&swq[h * 64];
    const float4* bq4 = (const float4*)&sbq[h * 64];
    const float4* wv4 = (const float4*)&swv[h * 64];
    const float4* bv4 = (const float4*)&sbv[h * 64];

    float a1 = 0.f, a2 = 0.f;
    #pragma unroll
    for (int d4 = 0; d4 < 16; d4++) {
        float4 q = wq4[d4], bq = bq4[d4], wv = wv4[d4], bv = bv4[d4];
        float v, qf;
        v = fmaf(xv, q.x, bq.x); qf = (v > 0.f) ? (v + 1.f) : __expf(v);
        a1 = fmaf(qf, wv.x, a1); a2 = fmaf(qf, bv.x, a2);
        v = fmaf(xv, q.y, bq.y); qf = (v > 0.f) ? (v + 1.f) : __expf(v);
        a1 = fmaf(qf, wv.y, a1); a2 = fmaf(qf, bv.y, a2);
        v = fmaf(xv, q.z, bq.z); qf = (v > 0.f) ? (v + 1.f) : __expf(v);
        a1 = fmaf(qf, wv.z, a1); a2 = fmaf(qf, bv.z, a2);
        v = fmaf(xv, q.w, bq.w); qf = (v > 0.f) ? (v + 1.f) : __expf(v);
        a1 = fmaf(qf, wv.w, a1); a2 = fmaf(qf, bv.w, a2);
    }
    const float s1 = sS1[h], s2 = sS2[h];
    sF[h][pl]     = fmaf(a1, s2, a2 * s1);   // alpha
    sF[8 + h][pl] = fmaf(a1, s1, 64.f * a2); // beta
    if (h == 0) sF[16][pl] = 1.f;
    __syncthreads();

    {
        size_t baseF = ((size_t)b * 16) * Pn + p0;
        int i = tid >> 6, pl2 = tid & 63;
        g_F[baseF + (size_t)i * Pn + pl2] = sF[i][pl2];
        g_F[baseF + (size_t)(i + 8) * Pn + pl2] = sF[i + 8][pl2];
    }
    {
        size_t baseH = ((size_t)b * 17) * Pn + p0;
        for (int o = tid; o < 17 * 64; o += 512) {
            int i = o >> 6, pl2 = o & 63;
            float s = 0.f;
            #pragma unroll
            for (int j = 0; j < 17; j++)
                s = fmaf(sG[i * 17 + j], sF[j][pl2], s);
            g_Hh[baseH + (size_t)i * Pn + pl2] = s;
        }
    }
}

// ---------------------------------------------------------------------------
// Kernel 3: bilinear GEMM (round-5 version, known good).
// ---------------------------------------------------------------------------
#define FMA2(acc64, a64, b64) \
    asm("fma.rn.f32x2 %0, %1, %2, %0;" : "+l"(acc64) : "l"(a64), "l"(b64))
#define UNPACK2(lo, hi, in64) do { \
    unsigned _u0, _u1; \
    asm("mov.b64 {%0, %1}, %2;" : "=r"(_u0), "=r"(_u1) : "l"(in64)); \
    lo = __uint_as_float(_u0); hi = __uint_as_float(_u1); } while (0)

__global__ void __launch_bounds__(256) kGemm(float* __restrict__ out)
{
    const int b = blockIdx.z;
    const int tq0 = blockIdx.x * 64;
    const int tp0 = blockIdx.y * 128;

    __shared__ __align__(16) float sFd[16][256];
    __shared__ __align__(16) float sHh[17][64];

    const int tid = threadIdx.x;
    const int lane = tid & 31, w = tid >> 5;
    const float* Fb = g_F + ((size_t)b * 16) * Pn;
    const float* Hb = g_Hh + ((size_t)b * 17) * Pn;

    #pragma unroll
    for (int rep = 0; rep < 2; rep++) {
        int idx = tid + rep * 256;
        int row = idx >> 5, c4 = (idx & 31) << 2;
        float4 v = *(const float4*)&Fb[(size_t)row * Pn + tp0 + c4];
        *(float4*)&sFd[row][c4 * 2]     = make_float4(v.x, v.x, v.y, v.y);
        *(float4*)&sFd[row][c4 * 2 + 4] = make_float4(v.z, v.z, v.w, v.w);
    }
    {
        int row = tid >> 4, c4 = (tid & 15) << 2;
        *(float4*)&sHh[row][c4] = *(const float4*)&Hb[(size_t)row * Pn + tq0 + c4];
        if (tid < 16) {
            int idx2 = tid + 256;
            int row2 = idx2 >> 4, c42 = (idx2 & 15) << 2;
            *(float4*)&sHh[row2][c42] = *(const float4*)&Hb[(size_t)row2 * Pn + tq0 + c42];
        }
    }
    __syncthreads();

    unsigned long long bq[16];
    #pragma unroll
    for (int k = 0; k < 16; k++)
        bq[k] = *(const unsigned long long*)&sHh[k][2 * lane];
    const unsigned long long hbias = *(const unsigned long long*)&sHh[16][2 * lane];

    unsigned long long acc[16];
    #pragma unroll
    for (int r = 0; r < 16; r++) acc[r] = hbias;

    const int rowbase = w * 16;
    #pragma unroll
    for (int k = 0; k < 16; k++) {
        const float* fr = &sFd[k][rowbase * 2];
        #pragma unroll
        for (int rp = 0; rp < 8; rp++) {
            ulonglong2 ad = *(const ulonglong2*)&fr[rp * 4];
            FMA2(acc[2 * rp],     ad.x, bq[k]);
            FMA2(acc[2 * rp + 1], ad.y, bq[k]);
        }
    }

    float* outb = out + (size_t)b * Pn * Pn + (size_t)(tp0 + rowbase) * Pn + tq0 + 2 * lane;
    #pragma unroll
    for (int r = 0; r < 16; r++) {
        float2 v;
        UNPACK2(v.x, v.y, acc[r]);
        *(float2*)&outb[(size_t)r * Pn] = v;
    }
}

// ---------------------------------------------------------------------------
// inputs: 0 x, 1 w_q, 2 b_q, 3 w_k, 4 b_k(unused), 5 w_v, 6 b_v, 7 w_mem,
//         8 w_u, 9 b_u, 10 w_v2, 11 b_v2
// ---------------------------------------------------------------------------
extern "C" void kernel_launch(void* const* d_in, const int* in_sizes, int n_in,
                              void* d_out, int out_size)
{
    const float* x    = (const float*)d_in[0];
    const float* w_q  = (const float*)d_in[1];
    const float* b_q  = (const float*)d_in[2];
    const float* w_k  = (const float*)d_in[3];
    const float* w_v  = (const float*)d_in[5];
    const float* b_v  = (const float*)d_in[6];
    const float* w_mem = (const float*)d_in[7];
    const float* w_u  = (const float*)d_in[8];
    const float* b_u  = (const float*)d_in[9];
    const float* w_v2 = (const float*)d_in[10];
    const float* b_v2 = (const float*)d_in[11];
    float* out = (float*)d_out;

    kPre<<<33, 512>>>(x, w_k, w_mem, w_u, b_u, w_v2, b_v2, w_v, b_v);
    kFeat<<<dim3(Pn / 64, Bx), 512>>>(x, w_q, b_q, w_v, b_v);
    kGemm<<<dim3(Pn / 64, Pn / 128, Bx), 256>>>(out);
}